// round 6
// baseline (speedup 1.0000x reference)
#include <cuda_runtime.h>
#include <cuda_bf16.h>
#include <cstdint>

// ---------------- problem constants ----------------
#define B_    16
#define CIN   512
#define COUT  512
#define HS    36
#define WS    36
#define HO    38
#define WO    38
#define MTOT  (HO*WO)      // 1444
#define WDIM  512
#define MDIM  64
#define TAPS  12
#define HOUT  36
#define WOUT  36
#define HW    (HS*WS)      // 1296
#define XSTR  1664         // padded xs plane stride (floats)

// ---------------- scratch ----------------
// g_wt: fragment-blocked B. 144 ktiles x 4 ntiles, each 4096 floats (16 KB):
//   off = (((k8*4 + wnq)*2 + ntp)*32 + lane)*4 + ntl*2 + r2
//   lane=(co&7)*4+(k&3), r2=(k>>2)&1, k8=(k&31)>>3, wnq=(co>>5)&3, ntp=(co>>4)&1, ntl=(co>>3)&1
__device__ float g_wt[144 * 4 * 4096];
__device__ float g_q  [COUT * CIN];
__device__ float g_sn [B_ * CIN];
__device__ float g_xsp[B_ * CIN * XSTR];        // zero-padded x*sn (tf32), linear-in-m addressing
__device__ float g_scale[B_ * COUT];
__device__ float g_bmod [B_ * COUT];
__device__ float g_y  [B_ * COUT * MTOT];

// ---------------- cp.async helpers ----------------
__device__ __forceinline__ uint32_t smem_u32(const void* p) {
    uint32_t a;
    asm("{ .reg .u64 t; cvta.to.shared.u64 t, %1; cvt.u32.u64 %0, t; }" : "=r"(a) : "l"(p));
    return a;
}
__device__ __forceinline__ void cp32(uint32_t dst, const void* src) {
    asm volatile("cp.async.ca.shared.global [%0], [%1], 4;" :: "r"(dst), "l"(src));
}
__device__ __forceinline__ void cp128(uint32_t dst, const void* src) {
    asm volatile("cp.async.cg.shared.global [%0], [%1], 16;" :: "r"(dst), "l"(src));
}
#define CP_COMMIT() asm volatile("cp.async.commit_group;" ::: "memory")
#define CP_WAIT1()  asm volatile("cp.async.wait_group 1;" ::: "memory")
#define CP_WAIT0()  asm volatile("cp.async.wait_group 0;" ::: "memory")

// ---------------- kernel 1: weight prep (fragment-blocked, nt-paired) ----------------
__global__ __launch_bounds__(256) void prep_kernel(const float* __restrict__ weight)
{
    int co = blockIdx.x;
    int tid = threadIdx.x;
    __shared__ float red[256];
    const float* wrow = weight + co * (CIN * 9);
    float s = 0.f;
    for (int i = tid; i < CIN * 9; i += 256) { float v = wrow[i]; s += v * v; }
    red[tid] = s; __syncthreads();
    for (int st = 128; st > 0; st >>= 1) { if (tid < st) red[tid] += red[tid + st]; __syncthreads(); }
    float wnorm = rsqrtf(red[0] / (float)(CIN * 9));

    int ntile  = co >> 7;
    int wnq    = (co >> 5) & 3;
    int ntp    = (co >> 4) & 1;
    int ntl    = (co >> 3) & 1;
    int lane_n = (co & 7) * 4;

    for (int cin = tid; cin < CIN; cin += 256) {
        float q = 0.f;
        #pragma unroll
        for (int tap = 0; tap < 9; ++tap) {
            float wv = wrow[cin * 9 + tap] * wnorm;
            q += wv * wv;
            unsigned t; asm("cvt.rna.tf32.f32 %0, %1;" : "=r"(t) : "f"(wv));
            int k = tap * CIN + cin;
            int s5 = k >> 5, kl = k & 31;
            int k8 = kl >> 3, r2 = (kl >> 2) & 1, lane = lane_n + (kl & 3);
            size_t off = (size_t)(s5 * 4 + ntile) * 4096
                       + (size_t)((((k8 * 4 + wnq) * 2 + ntp) * 32 + lane) * 4 + ntl * 2 + r2);
            g_wt[off] = __uint_as_float(t);
        }
        g_q[co * CIN + cin] = q;
    }
}

// ---------------- kernel 2: styles ----------------
__global__ __launch_bounds__(512) void style_kernel(
    const float* __restrict__ w, const float* __restrict__ msg,
    const float* __restrict__ aw, const float* __restrict__ ab,
    const float* __restrict__ bias, const float* __restrict__ msw,
    const float* __restrict__ mbw)
{
    int b = blockIdx.x;
    int tid = threadIdx.x;
    __shared__ float red[512];
    __shared__ float wS[WDIM];
    __shared__ float mS[MDIM];
    wS[tid] = w[b * WDIM + tid];
    if (tid < MDIM) mS[tid] = msg[b * MDIM + tid];
    __syncthreads();

    float s = ab[tid];
    const float* arow = aw + tid * WDIM;
    #pragma unroll 4
    for (int j = 0; j < WDIM; ++j) s += wS[j] * arow[j];
    float ms = 0.f;
    #pragma unroll
    for (int j = 0; j < MDIM; ++j) ms += mS[j] * msw[j * CIN + tid];
    s += 0.01f * ms;

    red[tid] = s * s; __syncthreads();
    for (int st = 256; st > 0; st >>= 1) { if (tid < st) red[tid] += red[tid + st]; __syncthreads(); }
    float rs = rsqrtf(red[0] / (float)CIN);
    g_sn[b * CIN + tid] = s * rs;

    float mb = 0.f;
    #pragma unroll
    for (int j = 0; j < MDIM; ++j) mb += mS[j] * mbw[j * COUT + tid];
    g_bmod[b * COUT + tid] = bias[tid] + 0.01f * mb;
}

// ---------------- kernel 2b: padded xs plane ----------------
// flat = pos - 78 = ih*38 + iw (iw in 0..37). value iff ih<36 && iw<36, else 0.
__global__ __launch_bounds__(256) void xsp_kernel(const float* __restrict__ x)
{
    int idx = blockIdx.x * 256 + threadIdx.x;
    if (idx >= B_ * CIN * XSTR) return;
    int bc  = idx / XSTR;
    int pos = idx - bc * XSTR;
    int flat = pos - 78;
    float v = 0.f;
    if (flat >= 0) {
        int ih = flat / 38;
        int iw = flat - ih * 38;
        if (ih < HS && iw < WS) {
            float t0 = x[(size_t)bc * HW + ih * WS + iw] * g_sn[bc];
            unsigned t; asm("cvt.rna.tf32.f32 %0, %1;" : "=r"(t) : "f"(t0));
            v = __uint_as_float(t);
        }
    }
    g_xsp[idx] = v;
}

// ---------------- kernel 3: demod (warp per (b,co)) ----------------
__global__ __launch_bounds__(256) void demod_kernel(const float* __restrict__ magema)
{
    int gw   = blockIdx.x * 8 + (threadIdx.x >> 5);
    int lane = threadIdx.x & 31;
    int b  = gw >> 9;
    int co = gw & 511;
    const float4* q  = (const float4*)(g_q  + (size_t)co * CIN);
    const float4* sn = (const float4*)(g_sn + (size_t)b  * CIN);
    float acc = 0.f;
    #pragma unroll
    for (int j = 0; j < 4; ++j) {
        float4 qv = q [lane + j * 32];
        float4 sv = sn[lane + j * 32];
        acc += sv.x * sv.x * qv.x + sv.y * sv.y * qv.y
             + sv.z * sv.z * qv.z + sv.w * sv.w * qv.w;
    }
    #pragma unroll
    for (int o = 16; o > 0; o >>= 1) acc += __shfl_xor_sync(0xFFFFFFFF, acc, o);
    if (lane == 0)
        g_scale[gw] = rsqrtf(acc + 1e-8f) * rsqrtf(magema[0]);
}

// ---------------- kernel 4: pipelined implicit-GEMM conv (fragment-major tiles) ----------------
#define BM 128
#define BN 128
#define A_BYTES 16384
#define B_BYTES 16384
#define STAGE_AB (A_BYTES + B_BYTES)   // 32768
#define NSTAGE 3
#define SM_TILES (NSTAGE * STAGE_AB)   // 98304
#define CONV_SMEM (SM_TILES + 1024)

__global__ __launch_bounds__(256, 2) void conv3_kernel()
{
    extern __shared__ char dsm[];
    int tid  = threadIdx.x;
    int warp = tid >> 5, lane = tid & 31;

    int m0    = blockIdx.x * BM;
    int ntile = blockIdx.y;
    int n0    = ntile * BN;
    int b     = blockIdx.z;

    uint32_t smemA[NSTAGE], smemB[NSTAGE];
    #pragma unroll
    for (int i = 0; i < NSTAGE; ++i) {
        smemA[i] = smem_u32(dsm + i * STAGE_AB);
        smemB[i] = smem_u32(dsm + i * STAGE_AB + A_BYTES);
    }
    float* scS = (float*)(dsm + SM_TILES);
    float* bvS = (float*)(dsm + SM_TILES + 512);

    if (tid < 128) {
        scS[tid] = g_scale[b * COUT + n0 + tid];
        bvS[tid] = g_bmod [b * COUT + n0 + tid];
    }

    // A-fill mapping
    int mloc  = tid & 127;
    int khalf = tid >> 7;                 // 0/1
    int f_wmq = mloc >> 6;
    int f_mtq = (mloc >> 4) & 3;
    int f_m8  = (mloc >> 3) & 1;
    int f_row = mloc & 7;
    // thread-constant part of fragment-major float offset
    uint32_t aCbase = (uint32_t)(khalf * 2048 + f_wmq * 512 + f_mtq * 128 + f_row * 16 + f_m8);
    int jrot = mloc & 15;

    const float* xb = g_xsp + (size_t)b * CIN * XSTR + 78 + m0 + mloc;

    int wmq = warp & 1;                   // m 64-half
    int wnq = warp >> 1;                  // n 32-quad

    float acc[4][4][4];
    #pragma unroll
    for (int a = 0; a < 4; ++a)
        #pragma unroll
        for (int c = 0; c < 4; ++c)
            #pragma unroll
            for (int r = 0; r < 4; ++r) acc[a][c][r] = 0.f;

    auto fill_stage = [&](int s) {
        int buf = s % NSTAGE;
        int tap = s >> 4;
        int kh = tap / 3, kw = tap % 3;
        int moff = (kh - 2) * 38 + (kw - 2);
        int c0 = (s & 15) * 32 + khalf * 16;
        const float* src0 = xb + moff + (size_t)c0 * XSTR - (size_t)(khalf * 16) * XSTR; // base for kl=khalf*16
        // note: kl = khalf*16 + je; cin = (s&15)*32 + kl = c0 - khalf*16 + kl
        uint32_t ad = smemA[buf];
        #pragma unroll
        for (int j = 0; j < 16; ++j) {
            int je  = (j + jrot) & 15;
            int kl  = khalf * 16 + je;
            int k8  = kl >> 3;
            uint32_t off = aCbase - (uint32_t)(khalf * 2048)
                         + (uint32_t)(k8 * 1024 + (je & 3) * 4 + ((je >> 2) & 1) * 2);
            cp32(ad + off * 4, src0 + (size_t)kl * XSTR);
        }
        // B: linear 16 KB copy
        const float* bsrc = g_wt + (size_t)(s * 4 + ntile) * 4096;
        #pragma unroll
        for (int j = 0; j < 4; ++j) {
            int chunk = tid + j * 256;
            cp128(smemB[buf] + (uint32_t)chunk * 16, bsrc + chunk * 4);
        }
        CP_COMMIT();
    };

    fill_stage(0);
    fill_stage(1);

    for (int s = 0; s < 144; ++s) {
        int buf = s % NSTAGE;
        if (s < 143) { CP_WAIT1(); } else { CP_WAIT0(); }
        __syncthreads();

        const float4* Af = (const float4*)(dsm + buf * STAGE_AB);
        const float4* Bf = (const float4*)(dsm + buf * STAGE_AB + A_BYTES);

        #pragma unroll
        for (int k8 = 0; k8 < 4; ++k8) {
            unsigned afr[4][4], bfr[4][2];
            #pragma unroll
            for (int mt = 0; mt < 4; ++mt) {
                float4 av = Af[((k8 * 2 + wmq) * 4 + mt) * 32 + lane];
                afr[mt][0] = __float_as_uint(av.x);
                afr[mt][1] = __float_as_uint(av.y);
                afr[mt][2] = __float_as_uint(av.z);
                afr[mt][3] = __float_as_uint(av.w);
            }
            #pragma unroll
            for (int ntp = 0; ntp < 2; ++ntp) {
                float4 bv = Bf[((k8 * 4 + wnq) * 2 + ntp) * 32 + lane];
                bfr[2 * ntp][0]     = __float_as_uint(bv.x);
                bfr[2 * ntp][1]     = __float_as_uint(bv.y);
                bfr[2 * ntp + 1][0] = __float_as_uint(bv.z);
                bfr[2 * ntp + 1][1] = __float_as_uint(bv.w);
            }
            #pragma unroll
            for (int mt = 0; mt < 4; ++mt)
                #pragma unroll
                for (int nt = 0; nt < 4; ++nt)
                    asm volatile(
                        "mma.sync.aligned.m16n8k8.row.col.f32.tf32.tf32.f32 "
                        "{%0,%1,%2,%3}, {%4,%5,%6,%7}, {%8,%9}, {%0,%1,%2,%3};"
                        : "+f"(acc[mt][nt][0]), "+f"(acc[mt][nt][1]),
                          "+f"(acc[mt][nt][2]), "+f"(acc[mt][nt][3])
                        : "r"(afr[mt][0]), "r"(afr[mt][1]), "r"(afr[mt][2]), "r"(afr[mt][3]),
                          "r"(bfr[nt][0]), "r"(bfr[nt][1]));
        }

        if (s + 2 < 144) fill_stage(s + 2);
    }

    // ---- epilogue: scale + bias, write g_y ----
    float* yb = g_y + (size_t)b * COUT * MTOT;
    int wm = wmq * 64;
    int wn = wnq * 32;
    #pragma unroll
    for (int mt = 0; mt < 4; ++mt) {
        int mr = m0 + wm + mt * 16 + (lane >> 2);
        #pragma unroll
        for (int nt = 0; nt < 4; ++nt) {
            int ncl = wn + nt * 8 + (lane & 3) * 2;
            int nc  = n0 + ncl;
            float s0 = scS[ncl],     b0v = bvS[ncl];
            float s1 = scS[ncl + 1], b1v = bvS[ncl + 1];
            if (mr < MTOT) {
                yb[(size_t)nc * MTOT + mr]       = acc[mt][nt][0] * s0 + b0v;
                yb[(size_t)(nc + 1) * MTOT + mr] = acc[mt][nt][1] * s1 + b1v;
            }
            if (mr + 8 < MTOT) {
                yb[(size_t)nc * MTOT + mr + 8]       = acc[mt][nt][2] * s0 + b0v;
                yb[(size_t)(nc + 1) * MTOT + mr + 8] = acc[mt][nt][3] * s1 + b1v;
            }
        }
    }
}

// ---------------- kernel 5: fused filter chain ----------------
__global__ __launch_bounds__(256) void filt_kernel(
    const float* __restrict__ fu_g, const float* __restrict__ fd_g,
    float* __restrict__ out)
{
    __shared__ float sm[11688];
    float* U = sm;                        // 82*40
    float* Y = sm + 3280;                 // 38*40
    float* Z = sm + 4800;                 // 82*84
    float* T = sm;                        // 36*84 (reuse U)

    int plane = blockIdx.x;
    int tid = threadIdx.x;

    float fu[TAPS], fdr[TAPS];
    #pragma unroll
    for (int i = 0; i < TAPS; ++i) { fu[i] = fu_g[i]; fdr[i] = fd_g[TAPS - 1 - i]; }

    const float* yp = g_y + (size_t)plane * MTOT;
    for (int i = tid; i < MTOT; i += 256) {
        int r = i / WO, c = i % WO;
        Y[r * 40 + c] = yp[i];
    }
    __syncthreads();

    for (int i = tid; i < 82 * 38; i += 256) {
        int n = i / 38, wc = i % 38;
        float a = 0.f;
        int j0 = n & 1;
        #pragma unroll
        for (int jj = 0; jj < 6; ++jj) {
            int j = j0 + 2 * jj;
            int iy = (n + 2 - j) >> 1;
            if ((unsigned)iy < 38u) a += fu[j] * Y[iy * 40 + wc];
        }
        U[n * 40 + wc] = a;
    }
    __syncthreads();

    for (int i = tid; i < 82 * 82; i += 256) {
        int n = i / 82, m = i % 82;
        float a = 0.f;
        int j0 = m & 1;
        #pragma unroll
        for (int jj = 0; jj < 6; ++jj) {
            int j = j0 + 2 * jj;
            int iy = (m + 2 - j) >> 1;
            if ((unsigned)iy < 38u) a += fu[j] * U[n * 40 + iy];
        }
        a *= 4.0f;
        a = (a >= 0.f ? a : 0.2f * a) * 1.4142135623730951f;
        a = fminf(fmaxf(a, -256.f), 256.f);
        Z[n * 84 + m] = a;
    }
    __syncthreads();

    for (int i = tid; i < 36 * 82; i += 256) {
        int r = i / 82, m = i % 82;
        float a = 0.f;
        #pragma unroll
        for (int t = 0; t < TAPS; ++t) a += fdr[t] * Z[(2 * r + t) * 84 + m];
        T[r * 84 + m] = a;
    }
    __syncthreads();

    float* op = out + (size_t)plane * (HOUT * WOUT);
    for (int i = tid; i < HOUT * WOUT; i += 256) {
        int r = i / WOUT, c = i % WOUT;
        float a = 0.f;
        #pragma unroll
        for (int t = 0; t < TAPS; ++t) a += fdr[t] * T[r * 84 + 2 * c + t];
        op[i] = a;
    }
}

// ---------------- launch ----------------
extern "C" void kernel_launch(void* const* d_in, const int* in_sizes, int n_in,
                              void* d_out, int out_size)
{
    const float* x      = (const float*)d_in[0];
    const float* w      = (const float*)d_in[1];
    const float* msg    = (const float*)d_in[2];
    const float* aw     = (const float*)d_in[3];
    const float* ab     = (const float*)d_in[4];
    const float* weight = (const float*)d_in[5];
    const float* bias   = (const float*)d_in[6];
    const float* msw    = (const float*)d_in[7];
    const float* mbw    = (const float*)d_in[8];
    const float* fu     = (const float*)d_in[9];
    const float* fd     = (const float*)d_in[10];
    const float* mag    = (const float*)d_in[11];
    float* outp = (float*)d_out;

    cudaFuncSetAttribute(conv3_kernel, cudaFuncAttributeMaxDynamicSharedMemorySize, CONV_SMEM);

    prep_kernel <<<COUT, 256>>>(weight);
    style_kernel<<<B_, 512>>>(w, msg, aw, ab, bias, msw, mbw);
    xsp_kernel  <<<(B_ * CIN * XSTR + 255) / 256, 256>>>(x);
    demod_kernel<<<1024, 256>>>(mag);
    conv3_kernel<<<dim3((MTOT + BM - 1) / BM, COUT / BN, B_), 256, CONV_SMEM>>>();
    filt_kernel <<<B_ * COUT, 256>>>(fu, fd, outp);
}

// round 8
// speedup vs baseline: 1.7374x; 1.7374x over previous
#include <cuda_runtime.h>
#include <cuda_fp16.h>
#include <cstdint>

// ---------------- problem constants ----------------
#define B_    16
#define CIN   512
#define COUT  512
#define HS    36
#define WS    36
#define HO    38
#define WO    38
#define MTOT  (HO*WO)      // 1444
#define WDIM  512
#define MDIM  64
#define TAPS  12
#define HOUT  36
#define WOUT  36
#define HW    (HS*WS)      // 1296
#define XSTR  1664         // padded plane stride (in half2 words)

// ---------------- scratch ----------------
// g_wth: fp16 fragment-blocked B. 144 ktiles x 4 ntiles, 4096 halves (8 KB) each.
//   word = (((k16*4 + wnq)*2 + ntp)*32 + lane)*4 + ntl*2 + khi ; half = word*2 + klo
__device__ __half  g_wth[144 * 4 * 4096];
__device__ float    g_q  [COUT * CIN];
__device__ float    g_sn [B_ * CIN];
__device__ uint32_t g_xa [B_ * 256 * XSTR + 256];   // half2(x*sn) pairs, padded planes
__device__ float    g_scale[B_ * COUT];
__device__ float    g_bmod [B_ * COUT];
__device__ float    g_y  [B_ * COUT * MTOT];

// ---------------- cp.async helpers ----------------
__device__ __forceinline__ uint32_t smem_u32(const void* p) {
    uint32_t a;
    asm("{ .reg .u64 t; cvta.to.shared.u64 t, %1; cvt.u32.u64 %0, t; }" : "=r"(a) : "l"(p));
    return a;
}
__device__ __forceinline__ void cp32(uint32_t dst, const void* src) {
    asm volatile("cp.async.ca.shared.global [%0], [%1], 4;" :: "r"(dst), "l"(src));
}
__device__ __forceinline__ void cp128(uint32_t dst, const void* src) {
    asm volatile("cp.async.cg.shared.global [%0], [%1], 16;" :: "r"(dst), "l"(src));
}
#define CP_COMMIT() asm volatile("cp.async.commit_group;" ::: "memory")
#define CP_WAIT1()  asm volatile("cp.async.wait_group 1;" ::: "memory")
#define CP_WAIT0()  asm volatile("cp.async.wait_group 0;" ::: "memory")

// ---------------- kernel 1: weight prep (fp16 fragment-blocked) ----------------
__global__ __launch_bounds__(256) void prep_kernel(const float* __restrict__ weight)
{
    int co = blockIdx.x;
    int tid = threadIdx.x;
    __shared__ float red[256];
    const float* wrow = weight + co * (CIN * 9);
    float s = 0.f;
    for (int i = tid; i < CIN * 9; i += 256) { float v = wrow[i]; s += v * v; }
    red[tid] = s; __syncthreads();
    for (int st = 128; st > 0; st >>= 1) { if (tid < st) red[tid] += red[tid + st]; __syncthreads(); }
    float wnorm = rsqrtf(red[0] / (float)(CIN * 9));

    int ntile  = co >> 7;
    int wnq    = (co >> 5) & 3;
    int ntp    = (co >> 4) & 1;
    int ntl    = (co >> 3) & 1;
    int nlane  = (co & 7) * 4;

    for (int cin = tid; cin < CIN; cin += 256) {
        float q = 0.f;
        #pragma unroll
        for (int tap = 0; tap < 9; ++tap) {
            float wv = wrow[cin * 9 + tap] * wnorm;
            q += wv * wv;
            int k = tap * CIN + cin;
            int s5 = k >> 5;
            int k16 = (k >> 4) & 1;
            int klc = k & 15;
            int khi = klc >> 3, kk = klc & 7;
            int lane = nlane + (kk >> 1);
            int klo = kk & 1;
            size_t word = (size_t)((((k16 * 4 + wnq) * 2 + ntp) * 32 + lane) * 4 + ntl * 2 + khi);
            g_wth[(size_t)(s5 * 4 + ntile) * 4096 + word * 2 + klo] = __float2half_rn(wv);
        }
        g_q[co * CIN + cin] = q;
    }
}

// ---------------- kernel 2: styles ----------------
__global__ __launch_bounds__(512) void style_kernel(
    const float* __restrict__ w, const float* __restrict__ msg,
    const float* __restrict__ aw, const float* __restrict__ ab,
    const float* __restrict__ bias, const float* __restrict__ msw,
    const float* __restrict__ mbw)
{
    int b = blockIdx.x;
    int tid = threadIdx.x;
    __shared__ float red[512];
    __shared__ float wS[WDIM];
    __shared__ float mS[MDIM];
    wS[tid] = w[b * WDIM + tid];
    if (tid < MDIM) mS[tid] = msg[b * MDIM + tid];
    __syncthreads();

    float s = ab[tid];
    const float* arow = aw + tid * WDIM;
    #pragma unroll 4
    for (int j = 0; j < WDIM; ++j) s += wS[j] * arow[j];
    float ms = 0.f;
    #pragma unroll
    for (int j = 0; j < MDIM; ++j) ms += mS[j] * msw[j * CIN + tid];
    s += 0.01f * ms;

    red[tid] = s * s; __syncthreads();
    for (int st = 256; st > 0; st >>= 1) { if (tid < st) red[tid] += red[tid + st]; __syncthreads(); }
    float rs = rsqrtf(red[0] / (float)CIN);
    g_sn[b * CIN + tid] = s * rs;

    float mb = 0.f;
    #pragma unroll
    for (int j = 0; j < MDIM; ++j) mb += mS[j] * mbw[j * COUT + tid];
    g_bmod[b * COUT + tid] = bias[tid] + 0.01f * mb;
}

// ---------------- kernel 2b: packed padded half2 planes ----------------
__global__ __launch_bounds__(256) void xa_kernel(const float* __restrict__ x)
{
    int idx = blockIdx.x * 256 + threadIdx.x;
    if (idx >= B_ * 256 * XSTR) return;
    int bcp = idx / XSTR;
    int pos = idx - bcp * XSTR;
    int b  = bcp >> 8;
    int cp = bcp & 255;
    uint32_t v = 0;
    int flat = pos - 78;
    if (flat >= 0) {
        int ih = flat / 38;
        int iw = flat - ih * 38;
        if (ih < HS && iw < WS) {
            int cin = cp * 2;
            int sp = ih * WS + iw;
            float f0 = x[((size_t)(b * CIN + cin)     ) * HW + sp] * g_sn[b * CIN + cin];
            float f1 = x[((size_t)(b * CIN + cin + 1) ) * HW + sp] * g_sn[b * CIN + cin + 1];
            __half2 h = __floats2half2_rn(f0, f1);
            v = *(uint32_t*)&h;
        }
    }
    g_xa[idx] = v;
}

// ---------------- kernel 3: demod (warp per (b,co)) ----------------
__global__ __launch_bounds__(256) void demod_kernel(const float* __restrict__ magema)
{
    int gw   = blockIdx.x * 8 + (threadIdx.x >> 5);
    int lane = threadIdx.x & 31;
    int b  = gw >> 9;
    int co = gw & 511;
    const float4* q  = (const float4*)(g_q  + (size_t)co * CIN);
    const float4* sn = (const float4*)(g_sn + (size_t)b  * CIN);
    float acc = 0.f;
    #pragma unroll
    for (int j = 0; j < 4; ++j) {
        float4 qv = q [lane + j * 32];
        float4 sv = sn[lane + j * 32];
        acc += sv.x * sv.x * qv.x + sv.y * sv.y * qv.y
             + sv.z * sv.z * qv.z + sv.w * sv.w * qv.w;
    }
    #pragma unroll
    for (int o = 16; o > 0; o >>= 1) acc += __shfl_xor_sync(0xFFFFFFFF, acc, o);
    if (lane == 0)
        g_scale[gw] = rsqrtf(acc + 1e-8f) * rsqrtf(magema[0]);
}

// ---------------- kernel 4: fp16 m16n8k16 pipelined implicit-GEMM conv ----------------
#define BM 128
#define BN 128
#define APITCH 136                 // uint words per k-pair row
#define A_BYTES (16 * APITCH * 4)  // 8704
#define B_BYTES 8192
#define STAGE_AB (A_BYTES + B_BYTES)   // 16896
#define NSTAGE 3
#define SM_TILES (NSTAGE * STAGE_AB)   // 50688
#define CONV_SMEM (SM_TILES + 1024)

__global__ __launch_bounds__(256, 2) void conv3_kernel()
{
    extern __shared__ char dsm[];
    int tid  = threadIdx.x;
    int warp = tid >> 5, lane = tid & 31;

    int m0    = blockIdx.x * BM;
    int ntile = blockIdx.y;
    int n0    = ntile * BN;
    int b     = blockIdx.z;

    uint32_t smemA[NSTAGE], smemB[NSTAGE];
    #pragma unroll
    for (int i = 0; i < NSTAGE; ++i) {
        smemA[i] = smem_u32(dsm + i * STAGE_AB);
        smemB[i] = smem_u32(dsm + i * STAGE_AB + A_BYTES);
    }
    float* scS = (float*)(dsm + SM_TILES);
    float* bvS = (float*)(dsm + SM_TILES + 512);

    if (tid < 128) {
        scS[tid] = g_scale[b * COUT + n0 + tid];
        bvS[tid] = g_bmod [b * COUT + n0 + tid];
    }

    // A-fill mapping: thread = (mloc 0..127, khalf 0..1); fills 8 k-pair rows
    int mloc  = tid & 127;
    int khalf = tid >> 7;
    const uint32_t* xb = g_xa + (size_t)b * 256 * XSTR + 78 + m0 + mloc;

    int wmq = warp & 1;                   // m 64-half
    int wnq = warp >> 1;                  // n 32-quad

    float acc[4][4][4];
    #pragma unroll
    for (int a = 0; a < 4; ++a)
        #pragma unroll
        for (int c = 0; c < 4; ++c)
            #pragma unroll
            for (int r = 0; r < 4; ++r) acc[a][c][r] = 0.f;

    auto fill_stage = [&](int s) {
        int buf = s % NSTAGE;
        int tap = s >> 4;
        int kh = tap / 3, kw = tap % 3;
        int moff = (kh - 2) * 38 + (kw - 2);
        // A: 8 cp32 per thread; dst words consecutive per warp
        uint32_t ad = smemA[buf];
        #pragma unroll
        for (int j = 0; j < 8; ++j) {
            int kp = khalf * 8 + j;                    // 0..15 (k-pair)
            int cp = (s & 15) * 16 + kp;               // cin-pair 0..255
            cp32(ad + (uint32_t)(kp * APITCH + mloc) * 4,
                 xb + (size_t)cp * XSTR + moff);
        }
        // B: 8 KB linear copy (2 cp128 per thread)
        const char* bsrc = (const char*)(g_wth + (size_t)(s * 4 + ntile) * 4096);
        cp128(smemB[buf] + (uint32_t)tid * 16,        bsrc + tid * 16);
        cp128(smemB[buf] + (uint32_t)(tid + 256) * 16, bsrc + (tid + 256) * 16);
        CP_COMMIT();
    };

    fill_stage(0);
    fill_stage(1);

    for (int s = 0; s < 144; ++s) {
        int buf = s % NSTAGE;
        if (s < 143) { CP_WAIT1(); } else { CP_WAIT0(); }
        __syncthreads();

        const uint32_t* Aw = (const uint32_t*)(dsm + buf * STAGE_AB);
        const uint4*    Bw = (const uint4*)(dsm + buf * STAGE_AB + A_BYTES);

        #pragma unroll
        for (int t = 0; t < 2; ++t) {                 // two k16 tiles
            unsigned afr[4][4], bfr[4][2];
            int kp = t * 8 + (lane & 3);
            int mb = wmq * 64 + (lane >> 2);
            #pragma unroll
            for (int mt = 0; mt < 4; ++mt) {
                int m = mb + mt * 16;
                afr[mt][0] = Aw[kp * APITCH + m];
                afr[mt][1] = Aw[kp * APITCH + m + 8];
                afr[mt][2] = Aw[(kp + 4) * APITCH + m];
                afr[mt][3] = Aw[(kp + 4) * APITCH + m + 8];
            }
            #pragma unroll
            for (int ntp = 0; ntp < 2; ++ntp) {
                uint4 bv = Bw[((t * 4 + wnq) * 2 + ntp) * 32 + lane];
                bfr[2 * ntp][0]     = bv.x;
                bfr[2 * ntp][1]     = bv.y;
                bfr[2 * ntp + 1][0] = bv.z;
                bfr[2 * ntp + 1][1] = bv.w;
            }
            #pragma unroll
            for (int mt = 0; mt < 4; ++mt)
                #pragma unroll
                for (int nt = 0; nt < 4; ++nt)
                    asm volatile(
                        "mma.sync.aligned.m16n8k16.row.col.f32.f16.f16.f32 "
                        "{%0,%1,%2,%3}, {%4,%5,%6,%7}, {%8,%9}, {%0,%1,%2,%3};"
                        : "+f"(acc[mt][nt][0]), "+f"(acc[mt][nt][1]),
                          "+f"(acc[mt][nt][2]), "+f"(acc[mt][nt][3])
                        : "r"(afr[mt][0]), "r"(afr[mt][1]), "r"(afr[mt][2]), "r"(afr[mt][3]),
                          "r"(bfr[nt][0]), "r"(bfr[nt][1]));
        }

        if (s + 2 < 144) fill_stage(s + 2);
    }

    // ---- epilogue: scale + bias, write g_y ----
    float* yb = g_y + (size_t)b * COUT * MTOT;
    int wm = wmq * 64;
    int wn = wnq * 32;
    #pragma unroll
    for (int mt = 0; mt < 4; ++mt) {
        int mr = m0 + wm + mt * 16 + (lane >> 2);
        #pragma unroll
        for (int nt = 0; nt < 4; ++nt) {
            int ncl = wn + nt * 8 + (lane & 3) * 2;
            int nc  = n0 + ncl;
            float s0 = scS[ncl],     b0v = bvS[ncl];
            float s1 = scS[ncl + 1], b1v = bvS[ncl + 1];
            if (mr < MTOT) {
                yb[(size_t)nc * MTOT + mr]       = acc[mt][nt][0] * s0 + b0v;
                yb[(size_t)(nc + 1) * MTOT + mr] = acc[mt][nt][1] * s1 + b1v;
            }
            if (mr + 8 < MTOT) {
                yb[(size_t)nc * MTOT + mr + 8]       = acc[mt][nt][2] * s0 + b0v;
                yb[(size_t)(nc + 1) * MTOT + mr + 8] = acc[mt][nt][3] * s1 + b1v;
            }
        }
    }
}

// ---------------- kernel 5: fused filter chain ----------------
__global__ __launch_bounds__(256) void filt_kernel(
    const float* __restrict__ fu_g, const float* __restrict__ fd_g,
    float* __restrict__ out)
{
    __shared__ float sm[11688];
    float* U = sm;                        // 82*40
    float* Y = sm + 3280;                 // 38*40
    float* Z = sm + 4800;                 // 82*84
    float* T = sm;                        // 36*84 (reuse U)

    int plane = blockIdx.x;
    int tid = threadIdx.x;

    float fu[TAPS], fdr[TAPS];
    #pragma unroll
    for (int i = 0; i < TAPS; ++i) { fu[i] = fu_g[i]; fdr[i] = fd_g[TAPS - 1 - i]; }

    const float* yp = g_y + (size_t)plane * MTOT;
    for (int i = tid; i < MTOT; i += 256) {
        int r = i / WO, c = i % WO;
        Y[r * 40 + c] = yp[i];
    }
    __syncthreads();

    for (int i = tid; i < 82 * 38; i += 256) {
        int n = i / 38, wc = i % 38;
        float a = 0.f;
        int j0 = n & 1;
        #pragma unroll
        for (int jj = 0; jj < 6; ++jj) {
            int j = j0 + 2 * jj;
            int iy = (n + 2 - j) >> 1;
            if ((unsigned)iy < 38u) a += fu[j] * Y[iy * 40 + wc];
        }
        U[n * 40 + wc] = a;
    }
    __syncthreads();

    for (int i = tid; i < 82 * 82; i += 256) {
        int n = i / 82, m = i % 82;
        float a = 0.f;
        int j0 = m & 1;
        #pragma unroll
        for (int jj = 0; jj < 6; ++jj) {
            int j = j0 + 2 * jj;
            int iy = (m + 2 - j) >> 1;
            if ((unsigned)iy < 38u) a += fu[j] * U[n * 40 + iy];
        }
        a *= 4.0f;
        a = (a >= 0.f ? a : 0.2f * a) * 1.4142135623730951f;
        a = fminf(fmaxf(a, -256.f), 256.f);
        Z[n * 84 + m] = a;
    }
    __syncthreads();

    for (int i = tid; i < 36 * 82; i += 256) {
        int r = i / 82, m = i % 82;
        float a = 0.f;
        #pragma unroll
        for (int t = 0; t < TAPS; ++t) a += fdr[t] * Z[(2 * r + t) * 84 + m];
        T[r * 84 + m] = a;
    }
    __syncthreads();

    float* op = out + (size_t)plane * (HOUT * WOUT);
    for (int i = tid; i < HOUT * WOUT; i += 256) {
        int r = i / WOUT, c = i % WOUT;
        float a = 0.f;
        #pragma unroll
        for (int t = 0; t < TAPS; ++t) a += fdr[t] * T[r * 84 + 2 * c + t];
        op[i] = a;
    }
}

// ---------------- launch ----------------
extern "C" void kernel_launch(void* const* d_in, const int* in_sizes, int n_in,
                              void* d_out, int out_size)
{
    const float* x      = (const float*)d_in[0];
    const float* w      = (const float*)d_in[1];
    const float* msg    = (const float*)d_in[2];
    const float* aw     = (const float*)d_in[3];
    const float* ab     = (const float*)d_in[4];
    const float* weight = (const float*)d_in[5];
    const float* bias   = (const float*)d_in[6];
    const float* msw    = (const float*)d_in[7];
    const float* mbw    = (const float*)d_in[8];
    const float* fu     = (const float*)d_in[9];
    const float* fd     = (const float*)d_in[10];
    const float* mag    = (const float*)d_in[11];
    float* outp = (float*)d_out;

    cudaFuncSetAttribute(conv3_kernel, cudaFuncAttributeMaxDynamicSharedMemorySize, CONV_SMEM);

    prep_kernel <<<COUT, 256>>>(weight);
    style_kernel<<<B_, 512>>>(w, msg, aw, ab, bias, msw, mbw);
    xa_kernel   <<<(B_ * 256 * XSTR + 255) / 256, 256>>>(x);
    demod_kernel<<<1024, 256>>>(mag);
    conv3_kernel<<<dim3((MTOT + BM - 1) / BM, COUT / BN, B_), 256, CONV_SMEM>>>();
    filt_kernel <<<B_ * COUT, 256>>>(fu, fd, outp);
}